// round 8
// baseline (speedup 1.0000x reference)
#include <cuda_runtime.h>

#define MAXN 131072
#define HID  128
#define ODIM 400
#define EPT  6              // edges per thread in edge-parallel kernels

// Scratch (no cudaMalloc allowed) — device globals, zeroed at module load.
// Every consumer restores the zero-invariant so graph replays are deterministic.
__device__ unsigned g_degi[MAXN];
__device__ float    g_dinv[MAXN];
__device__ float    g_y[MAXN];      // y[r] = dinv[r] * x[r]
__device__ float    g_sacc[MAXN];
__device__ float    g_tacc[MAXN];
__device__ float    g_v[HID];

// ---------------------------------------------------------------------------
// 1) degree count over destinations (col). 6 edges/thread -> single balanced
//    resident wave (grid ~1042 <= 1184 capacity at 8 CTA/SM).
__global__ void __launch_bounds__(256, 8)
k_deg(const int* __restrict__ col, int E, int vec_ok) {
    int t = blockIdx.x * blockDim.x + threadIdx.x;
    int e = t * EPT;
    if (vec_ok && e + EPT - 1 < E) {
        int2 c0 = *reinterpret_cast<const int2*>(col + e);
        int2 c1 = *reinterpret_cast<const int2*>(col + e + 2);
        int2 c2 = *reinterpret_cast<const int2*>(col + e + 4);
        atomicAdd(&g_degi[c0.x], 1u);
        atomicAdd(&g_degi[c0.y], 1u);
        atomicAdd(&g_degi[c1.x], 1u);
        atomicAdd(&g_degi[c1.y], 1u);
        atomicAdd(&g_degi[c2.x], 1u);
        atomicAdd(&g_degi[c2.y], 1u);
    } else if (e < E) {
        int lim = min(e + EPT, E);
        for (int k = e; k < lim; k++) atomicAdd(&g_degi[col[k]], 1u);
    }
}

// ---------------------------------------------------------------------------
// 2) dinv = rsqrt(deg + 1 self loop); y = dinv * x; re-zero degi for replay.
__global__ void k_dinv(const float* __restrict__ x, int n) {
    int i = blockIdx.x * blockDim.x + threadIdx.x;
    if (i < n) {
        float di = rsqrtf((float)(g_degi[i] + 1u));
        g_dinv[i] = di;
        g_y[i]    = di * x[i];
        g_degi[i] = 0u;                 // restore entry invariant
    }
}

// ---------------------------------------------------------------------------
// 3) fused edge pass: independent gathers + fire-and-forget REDs.
//    sacc[c] += y[r];  tacc[r] += dinv[c]
//    6 edges/thread -> one balanced resident wave.
__global__ void __launch_bounds__(256, 8)
k_edge(const int* __restrict__ row, const int* __restrict__ col,
       int E, int vec_ok) {
    int t = blockIdx.x * blockDim.x + threadIdx.x;
    int e = t * EPT;
    if (vec_ok && e + EPT - 1 < E) {
        int2 r0 = *reinterpret_cast<const int2*>(row + e);
        int2 r1 = *reinterpret_cast<const int2*>(row + e + 2);
        int2 r2 = *reinterpret_cast<const int2*>(row + e + 4);
        int2 c0 = *reinterpret_cast<const int2*>(col + e);
        int2 c1 = *reinterpret_cast<const int2*>(col + e + 2);
        int2 c2 = *reinterpret_cast<const int2*>(col + e + 4);
        // 12 independent gathers (full MLP, L2-resident), then 12 REDs
        float y0 = __ldg(&g_y[r0.x]);
        float y1 = __ldg(&g_y[r0.y]);
        float y2 = __ldg(&g_y[r1.x]);
        float y3 = __ldg(&g_y[r1.y]);
        float y4 = __ldg(&g_y[r2.x]);
        float y5 = __ldg(&g_y[r2.y]);
        float d0 = __ldg(&g_dinv[c0.x]);
        float d1 = __ldg(&g_dinv[c0.y]);
        float d2 = __ldg(&g_dinv[c1.x]);
        float d3 = __ldg(&g_dinv[c1.y]);
        float d4 = __ldg(&g_dinv[c2.x]);
        float d5 = __ldg(&g_dinv[c2.y]);
        atomicAdd(&g_sacc[c0.x], y0);
        atomicAdd(&g_sacc[c0.y], y1);
        atomicAdd(&g_sacc[c1.x], y2);
        atomicAdd(&g_sacc[c1.y], y3);
        atomicAdd(&g_sacc[c2.x], y4);
        atomicAdd(&g_sacc[c2.y], y5);
        atomicAdd(&g_tacc[r0.x], d0);
        atomicAdd(&g_tacc[r0.y], d1);
        atomicAdd(&g_tacc[r1.x], d2);
        atomicAdd(&g_tacc[r1.y], d3);
        atomicAdd(&g_tacc[r2.x], d4);
        atomicAdd(&g_tacc[r2.y], d5);
    } else if (e < E) {
        int lim = min(e + EPT, E);
        for (int k = e; k < lim; k++) {
            int r = row[k], c = col[k];
            atomicAdd(&g_sacc[c], __ldg(&g_y[r]));
            atomicAdd(&g_tacc[r], __ldg(&g_dinv[c]));
        }
    }
}

// ---------------------------------------------------------------------------
// 4) v[f] = sum_i t[i] * relu(s[i]*W1[f] + b1[f])
//    s[i] = di*(sacc[i] + y[i]);  t[i] = di*(tacc[i] + di)
//    Re-zeros sacc/tacc after consumption (replay invariant).
__global__ void k_v(const float* __restrict__ W1, const float* __restrict__ b1,
                    int n) {
    __shared__ float ssh[128];
    __shared__ float tsh[128];
    int f = threadIdx.x;
    float w  = W1[f];
    float bb = b1[f];
    float acc = 0.0f;

    for (int base = blockIdx.x * 128; base < n; base += gridDim.x * 128) {
        int i = base + f;
        float sv = 0.0f, tv = 0.0f;
        if (i < n) {
            float di = g_dinv[i];
            sv = di * (g_sacc[i] + g_y[i]);
            tv = di * (g_tacc[i] + di);
            g_sacc[i] = 0.0f;           // restore entry invariant
            g_tacc[i] = 0.0f;
        }
        __syncthreads();
        ssh[f] = sv;
        tsh[f] = tv;
        __syncthreads();
        int lim = min(128, n - base);
        #pragma unroll 8
        for (int j = 0; j < lim; j++) {
            float h = fmaxf(fmaf(ssh[j], w, bb), 0.0f);
            acc = fmaf(tsh[j], h, acc);
        }
    }
    atomicAdd(&g_v[f], acc);
}

// ---------------------------------------------------------------------------
// 5) out[o] = (1/N) * sum_f v[f]*W2[f,o] + b2[o]; re-zero g_v for replay.
__global__ void k_out(const float* __restrict__ W2, const float* __restrict__ b2,
                      float* __restrict__ out, int n) {
    __shared__ float vsh[HID];
    if (threadIdx.x < HID) {
        vsh[threadIdx.x] = g_v[threadIdx.x];
        g_v[threadIdx.x] = 0.0f;        // restore entry invariant
    }
    __syncthreads();
    int o = threadIdx.x;
    if (o < ODIM) {
        float acc = 0.0f;
        #pragma unroll 16
        for (int f = 0; f < HID; f++)
            acc = fmaf(vsh[f], W2[f * ODIM + o], acc);
        out[o] = acc * (1.0f / (float)n) + b2[o];
    }
}

// ---------------------------------------------------------------------------
extern "C" void kernel_launch(void* const* d_in, const int* in_sizes, int n_in,
                              void* d_out, int out_size) {
    const float* x  = (const float*)d_in[0];   // [N,1]
    const int*   ei = (const int*)d_in[1];     // [2,E]: row half then col half
    const float* W1 = (const float*)d_in[2];   // [1,128]
    const float* b1 = (const float*)d_in[3];   // [128]
    const float* W2 = (const float*)d_in[4];   // [128,400]
    const float* b2 = (const float*)d_in[5];   // [400]
    float* out = (float*)d_out;                // [400]

    int n = in_sizes[0];
    int E = in_sizes[1] / 2;
    const int* row = ei;
    const int* col = ei + E;
    // int2 path needs 8B alignment of both halves: E must be even
    int vec_ok = ((E & 1) == 0) ? 1 : 0;

    int nb_n = (n + 255) / 256;
    int eth  = (E + EPT - 1) / EPT;            // threads for edge kernels
    int nb_e = (eth + 255) / 256;              // ~1042 blocks: one resident wave

    k_deg <<<nb_e, 256>>>(col, E, vec_ok);
    k_dinv<<<nb_n, 256>>>(x, n);
    k_edge<<<nb_e, 256>>>(row, col, E, vec_ok);
    k_v   <<<448, 128>>>(W1, b1, n);
    k_out <<<1, 512>>>(W2, b2, out, n);
}

// round 10
// speedup vs baseline: 1.0260x; 1.0260x over previous
#include <cuda_runtime.h>

#define MAXN 131072
#define HID  128
#define ODIM 400

// Scratch (no cudaMalloc allowed) — device globals, zeroed at module load.
// Every consumer restores the zero-invariant so graph replays are deterministic.
__device__ unsigned g_degi[MAXN];
__device__ float    g_dinv[MAXN];
__device__ float    g_y[MAXN];      // y[r] = dinv[r] * x[r]
__device__ float    g_sacc[MAXN];
__device__ float    g_tacc[MAXN];
__device__ float    g_v[HID];

// ---------------------------------------------------------------------------
// 1) degree count over destinations (col). R7-proven shape: 4 edges/thread,
//    int4 index loads, grid ~1563.
__global__ void __launch_bounds__(256, 8)
k_deg(const int* __restrict__ col, int E, int vec_ok) {
    int i = blockIdx.x * blockDim.x + threadIdx.x;
    int e = i * 4;
    if (vec_ok && e + 3 < E) {
        int4 c = *reinterpret_cast<const int4*>(col + e);
        atomicAdd(&g_degi[c.x], 1u);
        atomicAdd(&g_degi[c.y], 1u);
        atomicAdd(&g_degi[c.z], 1u);
        atomicAdd(&g_degi[c.w], 1u);
    } else if (e < E) {
        int lim = min(e + 4, E);
        for (int k = e; k < lim; k++) atomicAdd(&g_degi[col[k]], 1u);
    }
}

// ---------------------------------------------------------------------------
// 2) dinv = rsqrt(deg + 1 self loop); y = dinv * x; re-zero degi for replay.
__global__ void k_dinv(const float* __restrict__ x, int n) {
    int i = blockIdx.x * blockDim.x + threadIdx.x;
    if (i < n) {
        float di = rsqrtf((float)(g_degi[i] + 1u));
        g_dinv[i] = di;
        g_y[i]    = di * x[i];
        g_degi[i] = 0u;                 // restore entry invariant
    }
}

// ---------------------------------------------------------------------------
// 3) fused edge pass (R7-proven shape): independent gathers + fire-and-forget
//    REDs. sacc[c] += y[r];  tacc[r] += dinv[c]
__global__ void __launch_bounds__(256, 8)
k_edge(const int* __restrict__ row, const int* __restrict__ col,
       int E, int vec_ok) {
    int i = blockIdx.x * blockDim.x + threadIdx.x;
    int e = i * 4;
    if (vec_ok && e + 3 < E) {
        int4 r = *reinterpret_cast<const int4*>(row + e);
        int4 c = *reinterpret_cast<const int4*>(col + e);
        // 8 independent gathers (full MLP, L2-resident), then 8 REDs
        float y0 = __ldg(&g_y[r.x]);
        float y1 = __ldg(&g_y[r.y]);
        float y2 = __ldg(&g_y[r.z]);
        float y3 = __ldg(&g_y[r.w]);
        float d0 = __ldg(&g_dinv[c.x]);
        float d1 = __ldg(&g_dinv[c.y]);
        float d2 = __ldg(&g_dinv[c.z]);
        float d3 = __ldg(&g_dinv[c.w]);
        atomicAdd(&g_sacc[c.x], y0);
        atomicAdd(&g_sacc[c.y], y1);
        atomicAdd(&g_sacc[c.z], y2);
        atomicAdd(&g_sacc[c.w], y3);
        atomicAdd(&g_tacc[r.x], d0);
        atomicAdd(&g_tacc[r.y], d1);
        atomicAdd(&g_tacc[r.z], d2);
        atomicAdd(&g_tacc[r.w], d3);
    } else if (e < E) {
        int lim = min(e + 4, E);
        for (int k = e; k < lim; k++) {
            int r = row[k], c = col[k];
            atomicAdd(&g_sacc[c], __ldg(&g_y[r]));
            atomicAdd(&g_tacc[r], __ldg(&g_dinv[c]));
        }
    }
}

// ---------------------------------------------------------------------------
// 4) v[f] = sum_i t[i] * relu(s[i]*W1[f] + b1[f])
//    s[i] = di*(sacc[i] + y[i]);  t[i] = di*(tacc[i] + di)
//    256 threads: tid%128 = feature, tid/128 = node sub-tile. 4 independent
//    accumulators break the FMA RAW chain. Re-zeros sacc/tacc for replay.
__global__ void __launch_bounds__(256, 8)
k_v(const float* __restrict__ W1, const float* __restrict__ b1, int n) {
    __shared__ float ssh[256];
    __shared__ float tsh[256];
    const int tid  = threadIdx.x;
    const int f    = tid & (HID - 1);
    const int half = tid >> 7;               // 0 or 1
    float w  = W1[f];
    float bb = b1[f];
    float a0 = 0.0f, a1 = 0.0f, a2 = 0.0f, a3 = 0.0f;

    for (int base = blockIdx.x * 256; base < n; base += gridDim.x * 256) {
        int i = base + tid;
        float sv = 0.0f, tv = 0.0f;
        if (i < n) {
            float di = g_dinv[i];
            sv = di * (g_sacc[i] + g_y[i]);
            tv = di * (g_tacc[i] + di);
            g_sacc[i] = 0.0f;           // restore entry invariant
            g_tacc[i] = 0.0f;
        }
        __syncthreads();
        ssh[tid] = sv;
        tsh[tid] = tv;
        __syncthreads();
        int lim  = min(256, n - base);
        int j0   = half * HID;
        int jend = min(lim, j0 + HID);
        int j = j0;
        for (; j + 3 < jend; j += 4) {
            float h0 = fmaxf(fmaf(ssh[j    ], w, bb), 0.0f);
            float h1 = fmaxf(fmaf(ssh[j + 1], w, bb), 0.0f);
            float h2 = fmaxf(fmaf(ssh[j + 2], w, bb), 0.0f);
            float h3 = fmaxf(fmaf(ssh[j + 3], w, bb), 0.0f);
            a0 = fmaf(tsh[j    ], h0, a0);
            a1 = fmaf(tsh[j + 1], h1, a1);
            a2 = fmaf(tsh[j + 2], h2, a2);
            a3 = fmaf(tsh[j + 3], h3, a3);
        }
        for (; j < jend; j++) {
            float h = fmaxf(fmaf(ssh[j], w, bb), 0.0f);
            a0 = fmaf(tsh[j], h, a0);
        }
        __syncthreads();
    }
    atomicAdd(&g_v[f], (a0 + a1) + (a2 + a3));
}

// ---------------------------------------------------------------------------
// 5) out[o] = (1/N) * sum_f v[f]*W2[f,o] + b2[o]; re-zero g_v for replay.
__global__ void k_out(const float* __restrict__ W2, const float* __restrict__ b2,
                      float* __restrict__ out, int n) {
    __shared__ float vsh[HID];
    if (threadIdx.x < HID) {
        vsh[threadIdx.x] = g_v[threadIdx.x];
        g_v[threadIdx.x] = 0.0f;        // restore entry invariant
    }
    __syncthreads();
    int o = threadIdx.x;
    if (o < ODIM) {
        float acc = 0.0f;
        #pragma unroll 16
        for (int f = 0; f < HID; f++)
            acc = fmaf(vsh[f], W2[f * ODIM + o], acc);
        out[o] = acc * (1.0f / (float)n) + b2[o];
    }
}

// ---------------------------------------------------------------------------
extern "C" void kernel_launch(void* const* d_in, const int* in_sizes, int n_in,
                              void* d_out, int out_size) {
    const float* x  = (const float*)d_in[0];   // [N,1]
    const int*   ei = (const int*)d_in[1];     // [2,E]: row half then col half
    const float* W1 = (const float*)d_in[2];   // [1,128]
    const float* b1 = (const float*)d_in[3];   // [128]
    const float* W2 = (const float*)d_in[4];   // [128,400]
    const float* b2 = (const float*)d_in[5];   // [400]
    float* out = (float*)d_out;                // [400]

    int n = in_sizes[0];
    int E = in_sizes[1] / 2;
    const int* row = ei;
    const int* col = ei + E;
    int vec_ok = ((E & 3) == 0) ? 1 : 0;       // col half stays 16B-aligned

    int nb_n = (n + 255) / 256;
    int eth  = (E + 3) / 4;                    // 4 edges per thread
    int nb_e = (eth + 255) / 256;              // ~1563 blocks (R7-proven)
    int nb_v = (n + 255) / 256;                // one 256-node round per block

    k_deg <<<nb_e, 256>>>(col, E, vec_ok);
    k_dinv<<<nb_n, 256>>>(x, n);
    k_edge<<<nb_e, 256>>>(row, col, E, vec_ok);
    k_v   <<<nb_v, 256>>>(W1, b1, n);
    k_out <<<1, 512>>>(W2, b2, out, n);
}

// round 11
// speedup vs baseline: 1.0408x; 1.0144x over previous
#include <cuda_runtime.h>

#define MAXN 131072
#define HID  128
#define ODIM 400

// Scratch (no cudaMalloc allowed) — device globals, zeroed at module load.
// Every consumer restores the zero-invariant so graph replays are deterministic.
__device__ unsigned g_degi[MAXN];
__device__ float    g_dinv[MAXN];
__device__ float    g_y[MAXN];      // y[r] = dinv[r] * x[r]
__device__ float    g_sacc[MAXN];
__device__ float    g_tacc[MAXN];
__device__ float    g_v[HID];

// ---------------------------------------------------------------------------
// 1) degree count over destinations (col). R7-proven shape: 4 edges/thread,
//    int4 index loads, grid ~1563.
__global__ void __launch_bounds__(256, 8)
k_deg(const int* __restrict__ col, int E, int vec_ok) {
    int i = blockIdx.x * blockDim.x + threadIdx.x;
    int e = i * 4;
    if (vec_ok && e + 3 < E) {
        int4 c = *reinterpret_cast<const int4*>(col + e);
        atomicAdd(&g_degi[c.x], 1u);
        atomicAdd(&g_degi[c.y], 1u);
        atomicAdd(&g_degi[c.z], 1u);
        atomicAdd(&g_degi[c.w], 1u);
    } else if (e < E) {
        int lim = min(e + 4, E);
        for (int k = e; k < lim; k++) atomicAdd(&g_degi[col[k]], 1u);
    }
}

// ---------------------------------------------------------------------------
// 2) dinv = rsqrt(deg + 1 self loop); y = dinv * x; re-zero degi for replay.
__global__ void k_dinv(const float* __restrict__ x, int n) {
    int i = blockIdx.x * blockDim.x + threadIdx.x;
    if (i < n) {
        float di = rsqrtf((float)(g_degi[i] + 1u));
        g_dinv[i] = di;
        g_y[i]    = di * x[i];
        g_degi[i] = 0u;                 // restore entry invariant
    }
}

// ---------------------------------------------------------------------------
// 3) fused edge pass (R7-proven shape): independent gathers + fire-and-forget
//    REDs. sacc[c] += y[r];  tacc[r] += dinv[c]
__global__ void __launch_bounds__(256, 8)
k_edge(const int* __restrict__ row, const int* __restrict__ col,
       int E, int vec_ok) {
    int i = blockIdx.x * blockDim.x + threadIdx.x;
    int e = i * 4;
    if (vec_ok && e + 3 < E) {
        int4 r = *reinterpret_cast<const int4*>(row + e);
        int4 c = *reinterpret_cast<const int4*>(col + e);
        // 8 independent gathers (full MLP, L2-resident), then 8 REDs
        float y0 = __ldg(&g_y[r.x]);
        float y1 = __ldg(&g_y[r.y]);
        float y2 = __ldg(&g_y[r.z]);
        float y3 = __ldg(&g_y[r.w]);
        float d0 = __ldg(&g_dinv[c.x]);
        float d1 = __ldg(&g_dinv[c.y]);
        float d2 = __ldg(&g_dinv[c.z]);
        float d3 = __ldg(&g_dinv[c.w]);
        atomicAdd(&g_sacc[c.x], y0);
        atomicAdd(&g_sacc[c.y], y1);
        atomicAdd(&g_sacc[c.z], y2);
        atomicAdd(&g_sacc[c.w], y3);
        atomicAdd(&g_tacc[r.x], d0);
        atomicAdd(&g_tacc[r.y], d1);
        atomicAdd(&g_tacc[r.z], d2);
        atomicAdd(&g_tacc[r.w], d3);
    } else if (e < E) {
        int lim = min(e + 4, E);
        for (int k = e; k < lim; k++) {
            int r = row[k], c = col[k];
            atomicAdd(&g_sacc[c], __ldg(&g_y[r]));
            atomicAdd(&g_tacc[r], __ldg(&g_dinv[c]));
        }
    }
}

// ---------------------------------------------------------------------------
// 4) v[f] = sum_i t[i] * relu(s[i]*W1[f] + b1[f])
//    s[i] = di*(sacc[i] + y[i]);  t[i] = di*(tacc[i] + di)
//    128-node tile per block (grid 782), 256 threads: f = tid&127,
//    half = tid>>7 processes 64 nodes. {s,t} packed float2, read as float4
//    (2 pairs per LDS.128). Fully unrolled, 4 independent accumulators.
//    Out-of-range nodes have t=0 -> contribute nothing.
__global__ void __launch_bounds__(256, 8)
k_v(const float* __restrict__ W1, const float* __restrict__ b1, int n) {
    __shared__ float2 st[128];          // {s, t} per node in tile
    __shared__ float  red[256];
    const int tid  = threadIdx.x;
    const int f    = tid & (HID - 1);
    const int half = tid >> 7;          // 0 or 1

    // tile load: first 128 threads compute (s,t) for 128 nodes
    if (tid < 128) {
        int i = blockIdx.x * 128 + tid;
        float sv = 0.0f, tv = 0.0f;
        if (i < n) {
            float di = g_dinv[i];
            sv = di * (g_sacc[i] + g_y[i]);
            tv = di * (g_tacc[i] + di);
            g_sacc[i] = 0.0f;           // restore entry invariant
            g_tacc[i] = 0.0f;
        }
        st[tid] = make_float2(sv, tv);
    }
    __syncthreads();

    float w  = W1[f];
    float bb = b1[f];
    float a0 = 0.0f, a1 = 0.0f, a2 = 0.0f, a3 = 0.0f;

    // each half processes 64 nodes: 32 float4 loads = 64 (s,t) pairs
    const float4* stv = reinterpret_cast<const float4*>(st + half * 64);
    #pragma unroll
    for (int k = 0; k < 32; k += 2) {
        float4 p = stv[k];              // {s0,t0,s1,t1}
        float4 q = stv[k + 1];          // {s2,t2,s3,t3}
        float h0 = fmaxf(fmaf(p.x, w, bb), 0.0f);
        float h1 = fmaxf(fmaf(p.z, w, bb), 0.0f);
        float h2 = fmaxf(fmaf(q.x, w, bb), 0.0f);
        float h3 = fmaxf(fmaf(q.z, w, bb), 0.0f);
        a0 = fmaf(p.y, h0, a0);
        a1 = fmaf(p.w, h1, a1);
        a2 = fmaf(q.y, h2, a2);
        a3 = fmaf(q.w, h3, a3);
    }

    // combine halves in smem, one RED per feature per block
    red[tid] = (a0 + a1) + (a2 + a3);
    __syncthreads();
    if (tid < 128) atomicAdd(&g_v[f], red[tid] + red[tid + 128]);
}

// ---------------------------------------------------------------------------
// 5) out[o] = (1/N) * sum_f v[f]*W2[f,o] + b2[o]; re-zero g_v for replay.
__global__ void k_out(const float* __restrict__ W2, const float* __restrict__ b2,
                      float* __restrict__ out, int n) {
    __shared__ float vsh[HID];
    if (threadIdx.x < HID) {
        vsh[threadIdx.x] = g_v[threadIdx.x];
        g_v[threadIdx.x] = 0.0f;        // restore entry invariant
    }
    __syncthreads();
    int o = threadIdx.x;
    if (o < ODIM) {
        float acc = 0.0f;
        #pragma unroll 16
        for (int f = 0; f < HID; f++)
            acc = fmaf(vsh[f], W2[f * ODIM + o], acc);
        out[o] = acc * (1.0f / (float)n) + b2[o];
    }
}

// ---------------------------------------------------------------------------
extern "C" void kernel_launch(void* const* d_in, const int* in_sizes, int n_in,
                              void* d_out, int out_size) {
    const float* x  = (const float*)d_in[0];   // [N,1]
    const int*   ei = (const int*)d_in[1];     // [2,E]: row half then col half
    const float* W1 = (const float*)d_in[2];   // [1,128]
    const float* b1 = (const float*)d_in[3];   // [128]
    const float* W2 = (const float*)d_in[4];   // [128,400]
    const float* b2 = (const float*)d_in[5];   // [400]
    float* out = (float*)d_out;                // [400]

    int n = in_sizes[0];
    int E = in_sizes[1] / 2;
    const int* row = ei;
    const int* col = ei + E;
    int vec_ok = ((E & 3) == 0) ? 1 : 0;       // col half stays 16B-aligned

    int nb_n = (n + 255) / 256;
    int eth  = (E + 3) / 4;                    // 4 edges per thread
    int nb_e = (eth + 255) / 256;              // ~1563 blocks (R7-proven)
    int nb_v = (n + 127) / 128;                // 782 blocks, 128-node tiles

    k_deg <<<nb_e, 256>>>(col, E, vec_ok);
    k_dinv<<<nb_n, 256>>>(x, n);
    k_edge<<<nb_e, 256>>>(row, col, E, vec_ok);
    k_v   <<<nb_v, 256>>>(W1, b1, n);
    k_out <<<1, 512>>>(W2, b2, out, n);
}